// round 6
// baseline (speedup 1.0000x reference)
#include <cuda_runtime.h>

#define BB 2
#define NQv 1024
#define NKv 1024
#define DD 512
#define HH 32

typedef unsigned long long ull;

// Scratch (no cudaMalloc allowed).
// g_tk2[pair*HH+h] = float2( tanh(hk[2p][h]+b1[h]), tanh(hk[2p+1][h]+b1[h]) )
// g_tq [row *HH+h] = tanh(hq[row][h])
__device__ __align__(16) float2 g_tk2[(BB * NKv / 2) * HH];
__device__ __align__(16) float  g_tq[(BB * NQv) * HH];

__device__ __forceinline__ float tanh_fast(float x) {
    float y; asm("tanh.approx.f32 %0, %1;" : "=f"(y) : "f"(x)); return y;
}
__device__ __forceinline__ float rcp_fast(float x) {
    float y; asm("rcp.approx.f32 %0, %1;" : "=f"(y) : "f"(x)); return y;
}
// Packed fp32x2 ops (Blackwell dual-rate fp32 path)
__device__ __forceinline__ ull f2_fma(ull a, ull b, ull c) {
    ull d; asm("fma.rn.f32x2 %0, %1, %2, %3;" : "=l"(d) : "l"(a), "l"(b), "l"(c)); return d;
}
__device__ __forceinline__ ull f2_mul(ull a, ull b) {
    ull d; asm("mul.rn.f32x2 %0, %1, %2;" : "=l"(d) : "l"(a), "l"(b)); return d;
}
__device__ __forceinline__ ull f2_add(ull a, ull b) {
    ull d; asm("add.rn.f32x2 %0, %1, %2;" : "=l"(d) : "l"(a), "l"(b)); return d;
}
__device__ __forceinline__ ull f2_pack(float lo, float hi) {
    ull d; asm("mov.b64 %0, {%1, %2};" : "=l"(d) : "f"(lo), "f"(hi)); return d;
}
__device__ __forceinline__ void f2_unpack(float& lo, float& hi, ull v) {
    asm("mov.b64 {%0, %1}, %2;" : "=f"(lo), "=f"(hi) : "l"(v));
}

#define ONE2  0x3F8000003F800000ULL
#define TWO2  0x4000000040000000ULL
#define NEG2  0xBF800000BF800000ULL
#define RCP_MAGIC 0x7EF311C3u

// ---------------------------------------------------------------------------
// Projection (R4 config): C[2048,32] = A[2048,512] @ W[512,32] per tensor.
// Block = 256 thr, 32 rows, K chunked by 128, both operands in smem.
// Epilogue now emits tanh-transformed outputs for the addition-identity
// score kernel: Tk (bias folded) as k-pairs, Tq scalar.
// ---------------------------------------------------------------------------
__global__ __launch_bounds__(256) void proj_kernel(
    const float* __restrict__ keys, const float* __restrict__ queries,
    const float* __restrict__ W1, const float* __restrict__ b1)
{
    __shared__ float as[32][128];   // A chunk (16 KB)
    __shared__ float ws[128][32];   // W chunk (16 KB)

    const int z    = blockIdx.y;
    const int tid  = threadIdx.x;
    const int h    = tid & 31;
    const int warp = tid >> 5;
    const int row0 = blockIdx.x * 32;
    const float* __restrict__ src = z ? queries : keys;

    float acc0 = 0.f, acc1 = 0.f, acc2 = 0.f, acc3 = 0.f;

    for (int c = 0; c < 4; ++c) {
        {
            const float4* __restrict__ ag =
                (const float4*)(src + (size_t)row0 * DD + c * 128);
            float4* av = (float4*)&as[0][0];
            #pragma unroll
            for (int i = 0; i < 4; ++i) {
                const int idx = tid + i * 256;
                const int r = idx >> 5, j = idx & 31;
                av[idx] = __ldg(&ag[(size_t)r * (DD / 4) + j]);
            }
        }
        {
            const float4* __restrict__ wg =
                (const float4*)(W1 + (size_t)(z * DD + c * 128) * HH);
            float4* wv = (float4*)&ws[0][0];
            #pragma unroll
            for (int i = 0; i < 4; ++i)
                wv[tid + i * 256] = __ldg(&wg[tid + i * 256]);
        }
        __syncthreads();

        #pragma unroll 8
        for (int d4 = 0; d4 < 32; ++d4) {
            const float4 a0 = *(const float4*)&as[4 * warp + 0][d4 * 4];
            const float4 a1 = *(const float4*)&as[4 * warp + 1][d4 * 4];
            const float4 a2 = *(const float4*)&as[4 * warp + 2][d4 * 4];
            const float4 a3 = *(const float4*)&as[4 * warp + 3][d4 * 4];
            const float w0  = ws[d4 * 4 + 0][h];
            const float w1v = ws[d4 * 4 + 1][h];
            const float w2v = ws[d4 * 4 + 2][h];
            const float w3v = ws[d4 * 4 + 3][h];
            acc0 = fmaf(a0.x, w0, acc0); acc0 = fmaf(a0.y, w1v, acc0);
            acc0 = fmaf(a0.z, w2v, acc0); acc0 = fmaf(a0.w, w3v, acc0);
            acc1 = fmaf(a1.x, w0, acc1); acc1 = fmaf(a1.y, w1v, acc1);
            acc1 = fmaf(a1.z, w2v, acc1); acc1 = fmaf(a1.w, w3v, acc1);
            acc2 = fmaf(a2.x, w0, acc2); acc2 = fmaf(a2.y, w1v, acc2);
            acc2 = fmaf(a2.z, w2v, acc2); acc2 = fmaf(a2.w, w3v, acc2);
            acc3 = fmaf(a3.x, w0, acc3); acc3 = fmaf(a3.y, w1v, acc3);
            acc3 = fmaf(a3.z, w2v, acc3); acc3 = fmaf(a3.w, w3v, acc3);
        }
        __syncthreads();
    }

    const int r0 = row0 + 4 * warp;
    if (z == 0) {
        const float bias = __ldg(&b1[h]);
        const int pair = r0 >> 1;
        g_tk2[(size_t)(pair + 0) * HH + h] =
            make_float2(tanh_fast(acc0 + bias), tanh_fast(acc1 + bias));
        g_tk2[(size_t)(pair + 1) * HH + h] =
            make_float2(tanh_fast(acc2 + bias), tanh_fast(acc3 + bias));
    } else {
        g_tq[(size_t)(r0 + 0) * HH + h] = tanh_fast(acc0);
        g_tq[(size_t)(r0 + 1) * HH + h] = tanh_fast(acc1);
        g_tq[(size_t)(r0 + 2) * HH + h] = tanh_fast(acc2);
        g_tq[(size_t)(r0 + 3) * HH + h] = tanh_fast(acc3);
    }
}

// ---------------------------------------------------------------------------
// Scoring v6 (rational hybrid): 64q x 32k tile, 256 thr, thread = 4q x 1
// k-pair (8 scores, packed as 4 f32x2 accumulators).
// tanh(a+b) = (Ta+Tb)/(1+Ta*Tb); reciprocal computed:
//   h % 3 != 2 -> rcp.approx.f32 on XU pipe      (22 of 32 h)
//   h % 3 == 2 -> bit-seed + 2 Newton, f32x2 FMA (10 of 32 h)
// so XU and FMA pipes run concurrently; XU load drops ~31%.
// ---------------------------------------------------------------------------
__global__ __launch_bounds__(256) void score_kernel(
    const float* __restrict__ W2, const float* __restrict__ b2,
    float* __restrict__ out)
{
    __shared__ float tqs[64][33];    // Tq, padded
    __shared__ ull   tks2[16][33];   // Tk k-pairs as packed f32x2, padded
    __shared__ float w2s[32];

    const int b   = blockIdx.z;
    const int q0  = blockIdx.y * 64;
    const int k0  = blockIdx.x * 32;
    const int tid = threadIdx.x;

    {
        const float* __restrict__ tq_g = g_tq + (size_t)(b * NQv + q0) * HH;
        #pragma unroll
        for (int it = 0; it < 8; ++it) {
            const int i = tid + it * 256;
            tqs[i >> 5][i & 31] = tq_g[i];
        }
        const ull* __restrict__ tk_g =
            (const ull*)(g_tk2 + (size_t)((b * NKv + k0) >> 1) * HH);
        #pragma unroll
        for (int it = 0; it < 2; ++it) {
            const int i = tid + it * 256;
            tks2[i >> 5][i & 31] = tk_g[i];
        }
        if (tid < 32) w2s[tid] = __ldg(&W2[tid]);
    }
    __syncthreads();

    const int kp = tid & 15;           // k-pair within tile
    const int qq = (tid >> 4) * 4;     // q base within tile

    ull acc[4];
    #pragma unroll
    for (int i = 0; i < 4; ++i) acc[i] = 0ULL;

    #pragma unroll
    for (int h = 0; h < HH; ++h) {
        const float w   = w2s[h];
        const ull   w2p = f2_pack(w, w);
        const ull   tk2 = tks2[kp][h];
        #pragma unroll
        for (int i = 0; i < 4; ++i) {
            const float tq = tqs[qq + i][h];
            const ull tq2  = f2_pack(tq, tq);
            const ull d2   = f2_fma(tq2, tk2, ONE2);   // 1 + Ta*Tb
            const ull n2   = f2_add(tq2, tk2);          // Ta + Tb
            float dl, dh;
            f2_unpack(dl, dh, d2);
            ull r2;
            if ((h % 3) == 2) {
                // FMA-pipe reciprocal: bit-trick seed (~5% rel) + 2 Newton
                const unsigned il = RCP_MAGIC - __float_as_uint(dl);
                const unsigned ih = RCP_MAGIC - __float_as_uint(dh);
                r2 = f2_pack(__uint_as_float(il), __uint_as_float(ih));
                const ull nd2 = f2_mul(d2, NEG2);
                r2 = f2_mul(r2, f2_fma(nd2, r2, TWO2));
                r2 = f2_mul(r2, f2_fma(nd2, r2, TWO2));
            } else {
                // XU-pipe reciprocal
                r2 = f2_pack(rcp_fast(dl), rcp_fast(dh));
            }
            const ull t2 = f2_mul(n2, r2);              // tanh(a+b)
            acc[i] = f2_fma(w2p, t2, acc[i]);
        }
    }

    const float bias = __ldg(b2);
    #pragma unroll
    for (int i = 0; i < 4; ++i) {
        float s0, s1;
        f2_unpack(s0, s1, acc[i]);
        float* __restrict__ o =
            out + (size_t)(b * NQv + q0 + qq + i) * NKv + k0 + 2 * kp;
        *(float2*)o = make_float2(s0 + bias, s1 + bias);
    }
}

extern "C" void kernel_launch(void* const* d_in, const int* in_sizes, int n_in,
                              void* d_out, int out_size)
{
    const float* keys    = (const float*)d_in[0];
    const float* queries = (const float*)d_in[1];
    const float* W1      = (const float*)d_in[2];
    const float* b1      = (const float*)d_in[3];
    const float* W2      = (const float*)d_in[4];
    const float* b2      = (const float*)d_in[5];
    float* out = (float*)d_out;

    proj_kernel<<<dim3(64, 2, 1), 256>>>(keys, queries, W1, b1);
    score_kernel<<<dim3(NKv / 32, NQv / 64, BB), 256>>>(W2, b2, out);
}

// round 7
// speedup vs baseline: 1.1777x; 1.1777x over previous
#include <cuda_runtime.h>

#define BB 2
#define NQv 1024
#define NKv 1024
#define DD 512
#define HH 32

// Split-K partial buffers (no cudaMalloc allowed). f32.
// g_hkp[ks][row*HH+h], g_hqp[ks][row*HH+h]; final value = sum over ks.
__device__ __align__(16) float g_hkp[2][BB * NKv * HH];
__device__ __align__(16) float g_hqp[2][BB * NQv * HH];

__device__ __forceinline__ float tanh_fast(float x) {
    float y; asm("tanh.approx.f32 %0, %1;" : "=f"(y) : "f"(x)); return y;
}

// ---------------------------------------------------------------------------
// Projection v7 (split-K): C[2048,32] = A[2048,512] @ W[512,32] per tensor.
// Grid (64 tiles, 2 tensors, 2 K-halves) = 256 blocks -> ~1.7 blocks/SM
// (~14 warps/SM vs 7 before). Block: 32 rows x 256 d, in two 128-d chunks;
// thread = 4 rows x 1 h (LDS/FMA = 0.5, crossbar parity). Partials to gmem;
// the score kernel sums the two halves during staging.
// ---------------------------------------------------------------------------
__global__ __launch_bounds__(256) void proj_kernel(
    const float* __restrict__ keys, const float* __restrict__ queries,
    const float* __restrict__ W1, const float* __restrict__ b1)
{
    __shared__ float as[32][128];   // A chunk (16 KB)
    __shared__ float ws[128][32];   // W chunk (16 KB)

    const int z    = blockIdx.y;
    const int ks   = blockIdx.z;
    const int tid  = threadIdx.x;
    const int h    = tid & 31;
    const int warp = tid >> 5;
    const int row0 = blockIdx.x * 32;
    const float* __restrict__ src = z ? queries : keys;

    float acc0 = 0.f, acc1 = 0.f, acc2 = 0.f, acc3 = 0.f;

    #pragma unroll
    for (int cc = 0; cc < 2; ++cc) {
        const int dchunk = ks * 256 + cc * 128;
        {   // A chunk: 32 rows x 32 float4 = 1024 float4, 4/thread
            const float4* __restrict__ ag =
                (const float4*)(src + (size_t)row0 * DD + dchunk);
            float4* av = (float4*)&as[0][0];
            #pragma unroll
            for (int i = 0; i < 4; ++i) {
                const int idx = tid + i * 256;
                const int r = idx >> 5, j = idx & 31;
                av[idx] = __ldg(&ag[(size_t)r * (DD / 4) + j]);
            }
        }
        {   // W chunk: 128 d x 32 h = 1024 float4, 4/thread, contiguous
            const float4* __restrict__ wg =
                (const float4*)(W1 + (size_t)(z * DD + dchunk) * HH);
            float4* wv = (float4*)&ws[0][0];
            #pragma unroll
            for (int i = 0; i < 4; ++i)
                wv[tid + i * 256] = __ldg(&wg[tid + i * 256]);
        }
        __syncthreads();

        #pragma unroll 8
        for (int d4 = 0; d4 < 32; ++d4) {
            const float4 a0 = *(const float4*)&as[4 * warp + 0][d4 * 4];
            const float4 a1 = *(const float4*)&as[4 * warp + 1][d4 * 4];
            const float4 a2 = *(const float4*)&as[4 * warp + 2][d4 * 4];
            const float4 a3 = *(const float4*)&as[4 * warp + 3][d4 * 4];
            const float w0  = ws[d4 * 4 + 0][h];
            const float w1v = ws[d4 * 4 + 1][h];
            const float w2v = ws[d4 * 4 + 2][h];
            const float w3v = ws[d4 * 4 + 3][h];
            acc0 = fmaf(a0.x, w0, acc0); acc0 = fmaf(a0.y, w1v, acc0);
            acc0 = fmaf(a0.z, w2v, acc0); acc0 = fmaf(a0.w, w3v, acc0);
            acc1 = fmaf(a1.x, w0, acc1); acc1 = fmaf(a1.y, w1v, acc1);
            acc1 = fmaf(a1.z, w2v, acc1); acc1 = fmaf(a1.w, w3v, acc1);
            acc2 = fmaf(a2.x, w0, acc2); acc2 = fmaf(a2.y, w1v, acc2);
            acc2 = fmaf(a2.z, w2v, acc2); acc2 = fmaf(a2.w, w3v, acc2);
            acc3 = fmaf(a3.x, w0, acc3); acc3 = fmaf(a3.y, w1v, acc3);
            acc3 = fmaf(a3.z, w2v, acc3); acc3 = fmaf(a3.w, w3v, acc3);
        }
        __syncthreads();
    }

    // Fold b1 into the ks==0 partial of hk only.
    const float bias = (z == 0 && ks == 0) ? __ldg(&b1[h]) : 0.f;
    float* __restrict__ dst = (z == 0) ? g_hkp[ks] : g_hqp[ks];
    const int r0 = row0 + 4 * warp;
    dst[(size_t)(r0 + 0) * HH + h] = acc0 + bias;
    dst[(size_t)(r0 + 1) * HH + h] = acc1 + bias;
    dst[(size_t)(r0 + 2) * HH + h] = acc2 + bias;
    dst[(size_t)(r0 + 3) * HH + h] = acc3 + bias;
}

// ---------------------------------------------------------------------------
// Scoring (R2 config, measured 20.38us): 64q x 32k tile, 256 thr, thread =
// 4q x 2k. Staging sums the two split-K partials. f32 tanh on XU pipe.
// ---------------------------------------------------------------------------
__global__ __launch_bounds__(256) void score_kernel(
    const float* __restrict__ W2, const float* __restrict__ b2,
    float* __restrict__ out)
{
    __shared__ float hqs[64][32];
    __shared__ float hks[32][33];
    __shared__ float w2s[32];

    const int b   = blockIdx.z;
    const int q0  = blockIdx.y * 64;
    const int k0  = blockIdx.x * 32;
    const int tid = threadIdx.x;

    {
        // hq tile: 64*32 floats = 512 float4; sum two partials
        const size_t qoff = (size_t)(b * NQv + q0) * HH;
        const float4* __restrict__ hq0 = (const float4*)(g_hqp[0] + qoff);
        const float4* __restrict__ hq1 = (const float4*)(g_hqp[1] + qoff);
        float4* hqv = (float4*)&hqs[0][0];
        #pragma unroll
        for (int it = 0; it < 2; ++it) {
            const int i = tid + it * 256;
            const float4 v0 = __ldg(&hq0[i]);
            const float4 v1 = __ldg(&hq1[i]);
            hqv[i] = make_float4(v0.x + v1.x, v0.y + v1.y,
                                 v0.z + v1.z, v0.w + v1.w);
        }
        // hk tile: 32*32 floats, scalar into padded array; sum two partials
        const size_t koff = (size_t)(b * NKv + k0) * HH;
        const float* __restrict__ hk0 = g_hkp[0] + koff;
        const float* __restrict__ hk1 = g_hkp[1] + koff;
        #pragma unroll
        for (int it = 0; it < 4; ++it) {
            const int i = tid + it * 256;
            hks[i >> 5][i & 31] = __ldg(&hk0[i]) + __ldg(&hk1[i]);
        }
        if (tid < 32) w2s[tid] = __ldg(&W2[tid]);
    }
    __syncthreads();

    const int kk = (tid & 15) * 2;
    const int qq = (tid >> 4) * 4;

    float a00 = 0.f, a01 = 0.f, a10 = 0.f, a11 = 0.f;
    float a20 = 0.f, a21 = 0.f, a30 = 0.f, a31 = 0.f;

    #pragma unroll
    for (int h = 0; h < HH; ++h) {
        const float w   = w2s[h];
        const float bk0 = hks[kk][h];
        const float bk1 = hks[kk + 1][h];
        const float q0v = hqs[qq + 0][h];
        const float q1v = hqs[qq + 1][h];
        const float q2v = hqs[qq + 2][h];
        const float q3v = hqs[qq + 3][h];
        a00 = fmaf(w, tanh_fast(q0v + bk0), a00);
        a01 = fmaf(w, tanh_fast(q0v + bk1), a01);
        a10 = fmaf(w, tanh_fast(q1v + bk0), a10);
        a11 = fmaf(w, tanh_fast(q1v + bk1), a11);
        a20 = fmaf(w, tanh_fast(q2v + bk0), a20);
        a21 = fmaf(w, tanh_fast(q2v + bk1), a21);
        a30 = fmaf(w, tanh_fast(q3v + bk0), a30);
        a31 = fmaf(w, tanh_fast(q3v + bk1), a31);
    }

    const float bias = __ldg(b2);
    float* __restrict__ o =
        out + (size_t)(b * NQv + q0 + qq) * NKv + k0 + kk;
    *(float2*)(o + 0 * NKv) = make_float2(a00 + bias, a01 + bias);
    *(float2*)(o + 1 * NKv) = make_float2(a10 + bias, a11 + bias);
    *(float2*)(o + 2 * NKv) = make_float2(a20 + bias, a21 + bias);
    *(float2*)(o + 3 * NKv) = make_float2(a30 + bias, a31 + bias);
}

extern "C" void kernel_launch(void* const* d_in, const int* in_sizes, int n_in,
                              void* d_out, int out_size)
{
    const float* keys    = (const float*)d_in[0];
    const float* queries = (const float*)d_in[1];
    const float* W1      = (const float*)d_in[2];
    const float* b1      = (const float*)d_in[3];
    const float* W2      = (const float*)d_in[4];
    const float* b2      = (const float*)d_in[5];
    float* out = (float*)d_out;

    // (64 row-tiles, 2 tensors, 2 K-halves) = 256 blocks
    proj_kernel<<<dim3(64, 2, 2), 256>>>(keys, queries, W1, b1);
    score_kernel<<<dim3(NKv / 32, NQv / 64, BB), 256>>>(W2, b2, out);
}